// round 1
// baseline (speedup 1.0000x reference)
#include <cuda_runtime.h>

#define BB 2
#define CC 512
#define HH 256
#define WW 256
#define EPSV 1e-5f

// ---------------- scratch (device globals; no allocations allowed) ----------
__device__ float g_y1[BB * CC * WW];     // [b][c][w]
__device__ float g_y2[BB * CC * HH];     // [b][c][h]
__device__ float g_dot[CC * BB];         // flat [c][b]; reinterpreted as num[b][k]
__device__ float g_h[BB * 2 * CC];       // [b][1024]
__device__ float g_logits[BB * CC];      // [b][c]
__device__ float g_scale[BB * CC];       // [b][c]

// ============================================================================
// k1: per-(b,c) plane, compute y1[w] = sum_h x[h][w]*w1[h]  (column matvec)
//                         and y2[h] = sum_w x[h][w]*w2[w]  (row matvec)
// Single pass over x (268 MB). grid = B*C = 1024, block = 256.
// Thread t: r = t>>6 selects row phase (rows r, r+4, ..., r+252),
//           q = t&63 selects column quad (cols 4q..4q+3).
// Warp = 32 lanes, all same row per iteration -> butterfly reduce gives the
// warp's 128-column partial of y2[row]; lane (i&31) banks it in a register.
// ============================================================================
__global__ __launch_bounds__(256) void k1(const float* __restrict__ x,
                                          const float* __restrict__ w1,
                                          const float* __restrict__ w2) {
    int bc = blockIdx.x;                 // b*CC + c
    int c  = bc & (CC - 1);
    const float4* plane = reinterpret_cast<const float4*>(x) + (size_t)bc * (HH * WW / 4);

    __shared__ float  w1s[HH];
    __shared__ float  w2s[WW];
    __shared__ float  y2part[HH][2];     // per-row partials from the two warp-halves
    __shared__ float4 acc1s[256];        // y1 partials, [r][q]

    int t = threadIdx.x;
    w1s[t] = w1[c * HH + t];             // w1: (C,1,H,1) -> c*H + h
    w2s[t] = w2[c * WW + t];             // w2: (C,1,1,W) -> c*W + w
    __syncthreads();

    int r    = t >> 6;
    int q    = t & 63;
    int lane = t & 31;
    int par  = (t >> 5) & 1;             // which half of the row this warp covers

    float4 w2q  = reinterpret_cast<const float4*>(w2s)[q];
    float4 acc1 = make_float4(0.f, 0.f, 0.f, 0.f);
    float  y2acc[2];

    #pragma unroll
    for (int half = 0; half < 2; ++half) {
        float acc = 0.f;
        #pragma unroll 8
        for (int ii = 0; ii < 32; ++ii) {
            int i   = half * 32 + ii;
            int row = 4 * i + r;
            float4 v   = plane[row * (WW / 4) + q];
            float  w1v = w1s[row];
            acc1.x = fmaf(v.x, w1v, acc1.x);
            acc1.y = fmaf(v.y, w1v, acc1.y);
            acc1.z = fmaf(v.z, w1v, acc1.z);
            acc1.w = fmaf(v.w, w1v, acc1.w);
            float p = v.x * w2q.x + v.y * w2q.y + v.z * w2q.z + v.w * w2q.w;
            #pragma unroll
            for (int off = 16; off; off >>= 1)
                p += __shfl_xor_sync(0xffffffffu, p, off);
            if (lane == ii) acc += p;    // all lanes hold the warp sum; lane ii banks it
        }
        y2acc[half] = acc;
    }

    // scatter y2 partials: lane l holds rows 4*l + r and 4*(32+l) + r
    y2part[4 * lane        + r][par] = y2acc[0];
    y2part[4 * (32 + lane) + r][par] = y2acc[1];
    acc1s[t] = acc1;                     // t == r*64 + q
    __syncthreads();

    g_y2[bc * HH + t] = y2part[t][0] + y2part[t][1];

    if (t < 64) {
        float4 a0 = acc1s[t], a1 = acc1s[64 + t], a2 = acc1s[128 + t], a3 = acc1s[192 + t];
        float4 o;
        o.x = (a0.x + a1.x) + (a2.x + a3.x);
        o.y = (a0.y + a1.y) + (a2.y + a3.y);
        o.z = (a0.z + a1.z) + (a2.z + a3.z);
        o.w = (a0.w + a1.w) + (a2.w + a3.w);
        reinterpret_cast<float4*>(g_y1 + (size_t)bc * WW)[t] = o;
    }
}

// ============================================================================
// block-wide sum over 256 threads (8 warps)
// ============================================================================
__device__ __forceinline__ float blockSum256(float v, float* sh) {
    #pragma unroll
    for (int off = 16; off; off >>= 1) v += __shfl_xor_sync(0xffffffffu, v, off);
    int lane = threadIdx.x & 31, w = threadIdx.x >> 5;
    if (lane == 0) sh[w] = v;
    __syncthreads();
    float res;
    if (threadIdx.x == 0) {
        float s = sh[0];
        #pragma unroll
        for (int i = 1; i < 8; ++i) s += sh[i];
        sh[0] = s;
    }
    __syncthreads();
    res = sh[0];
    __syncthreads();
    return res;
}

// ============================================================================
// k2: per-channel BN stats (biased, over B*256 = 512 values), ReLU, dot.
// grid = C = 512, block = 256. dot stored flat [c][b] so that the reference's
// reshape(b, c) of the [c, b] matrix is a plain linear reinterpret.
// ============================================================================
__global__ __launch_bounds__(256) void k2(const float* __restrict__ g1, const float* __restrict__ b1,
                                          const float* __restrict__ g2, const float* __restrict__ b2) {
    __shared__ float sh[8];
    int c = blockIdx.x, t = threadIdx.x;

    float a10 = g_y1[c * WW + t];
    float a11 = g_y1[CC * WW + c * WW + t];
    float a20 = g_y2[c * HH + t];
    float a21 = g_y2[CC * HH + c * HH + t];

    float S1 = blockSum256(a10 + a11, sh);
    float Q1 = blockSum256(a10 * a10 + a11 * a11, sh);
    float S2 = blockSum256(a20 + a21, sh);
    float Q2 = blockSum256(a20 * a20 + a21 * a21, sh);

    const float invn = 1.f / (float)(BB * WW);  // 1/512
    float m1 = S1 * invn, v1 = Q1 * invn - m1 * m1;
    float m2 = S2 * invn, v2 = Q2 * invn - m2 * m2;

    float r1 = rsqrtf(v1 + EPSV) * g1[c];
    float c1 = b1[c] - m1 * r1;
    float r2 = rsqrtf(v2 + EPSV) * g2[c];
    float c2 = b2[c] - m2 * r2;

    float x10 = fmaxf(0.f, fmaf(a10, r1, c1));
    float x11 = fmaxf(0.f, fmaf(a11, r1, c1));
    float x20 = fmaxf(0.f, fmaf(a20, r2, c2));
    float x21 = fmaxf(0.f, fmaf(a21, r2, c2));

    float d0 = blockSum256(x10 * x20, sh);
    float d1 = blockSum256(x11 * x21, sh);

    if (t == 0) {
        g_dot[c * BB + 0] = d0;
        g_dot[c * BB + 1] = d1;
    }
}

// ============================================================================
// linear layer: out[b][j] = bias[j] + sum_k inp[b][k] * wgt[j][k]
// warp per output j (coalesced weight reads), input cached in smem.
// ============================================================================
__device__ __forceinline__ void linear_body(const float* __restrict__ inp,
                                            const float* __restrict__ wgt,
                                            const float* __restrict__ bias,
                                            float* __restrict__ outp,
                                            int K, int J) {
    __shared__ float ins[2 * 1024];
    for (int k = threadIdx.x; k < 2 * K; k += blockDim.x) ins[k] = inp[k];
    __syncthreads();

    int warpId = threadIdx.x >> 5, lane = threadIdx.x & 31;
    int j = blockIdx.x * (blockDim.x >> 5) + warpId;
    if (j < J) {
        float a0 = 0.f, a1 = 0.f;
        for (int k = lane; k < K; k += 32) {
            float wv = wgt[j * K + k];
            a0 = fmaf(wv, ins[k], a0);
            a1 = fmaf(wv, ins[K + k], a1);
        }
        #pragma unroll
        for (int off = 16; off; off >>= 1) {
            a0 += __shfl_xor_sync(0xffffffffu, a0, off);
            a1 += __shfl_xor_sync(0xffffffffu, a1, off);
        }
        if (lane == 0) {
            outp[j]     = a0 + bias[j];
            outp[J + j] = a1 + bias[j];
        }
    }
}

__global__ __launch_bounds__(256) void k3a(const float* __restrict__ lw1, const float* __restrict__ lb1) {
    linear_body(g_dot, lw1, lb1, g_h, CC, 2 * CC);          // [2,512] @ [1024,512]^T
}
__global__ __launch_bounds__(256) void k3b(const float* __restrict__ lw2, const float* __restrict__ lb2) {
    linear_body(g_h, lw2, lb2, g_logits, 2 * CC, CC);       // [2,1024] @ [512,1024]^T
}

// ============================================================================
// k3c: stable softmax over axis 1. grid = B, block = 512.
// ============================================================================
__global__ __launch_bounds__(512) void k3c() {
    __shared__ float sh[16];
    int b = blockIdx.x, t = threadIdx.x;
    int lane = t & 31, w = t >> 5;

    float v = g_logits[b * CC + t];

    float m = v;
    #pragma unroll
    for (int off = 16; off; off >>= 1) m = fmaxf(m, __shfl_xor_sync(0xffffffffu, m, off));
    if (lane == 0) sh[w] = m;
    __syncthreads();
    if (t == 0) {
        float mm = sh[0];
        #pragma unroll
        for (int i = 1; i < 16; ++i) mm = fmaxf(mm, sh[i]);
        sh[0] = mm;
    }
    __syncthreads();
    m = sh[0];
    __syncthreads();

    float e = expf(v - m);
    float s = e;
    #pragma unroll
    for (int off = 16; off; off >>= 1) s += __shfl_xor_sync(0xffffffffu, s, off);
    if (lane == 0) sh[w] = s;
    __syncthreads();
    if (t == 0) {
        float ss = sh[0];
        #pragma unroll
        for (int i = 1; i < 16; ++i) ss += sh[i];
        sh[0] = ss;
    }
    __syncthreads();
    s = sh[0];

    g_scale[b * CC + t] = e / s;
}

// ============================================================================
// k4: out = x * scale[b,c]. grid = 4096 (4 CTAs per plane), block = 256, float4.
// ============================================================================
__global__ __launch_bounds__(256) void k4(const float* __restrict__ x, float* __restrict__ out) {
    int blk  = blockIdx.x;
    int bc   = blk >> 2;                 // plane index == b*CC + c == scale index
    int part = blk & 3;
    float s = g_scale[bc];

    const float4* xp = reinterpret_cast<const float4*>(x)   + (size_t)bc * (HH * WW / 4) + part * 4096;
    float4*       op = reinterpret_cast<float4*>(out)       + (size_t)bc * (HH * WW / 4) + part * 4096;

    #pragma unroll 4
    for (int i = threadIdx.x; i < 4096; i += 256) {
        float4 v = xp[i];
        v.x *= s; v.y *= s; v.z *= s; v.w *= s;
        op[i] = v;
    }
}

// ============================================================================
extern "C" void kernel_launch(void* const* d_in, const int* in_sizes, int n_in,
                              void* d_out, int out_size) {
    const float* x   = (const float*)d_in[0];
    const float* w1  = (const float*)d_in[1];
    const float* w2  = (const float*)d_in[2];
    const float* g1  = (const float*)d_in[3];
    const float* b1  = (const float*)d_in[4];
    const float* g2  = (const float*)d_in[5];
    const float* b2  = (const float*)d_in[6];
    const float* lw1 = (const float*)d_in[7];
    const float* lb1 = (const float*)d_in[8];
    const float* lw2 = (const float*)d_in[9];
    const float* lb2 = (const float*)d_in[10];
    float* out = (float*)d_out;

    k1<<<BB * CC, 256>>>(x, w1, w2);
    k2<<<CC, 256>>>(g1, b1, g2, b2);
    k3a<<<(2 * CC) / 8, 256>>>(lw1, lb1);   // 128 CTAs, warp per output row
    k3b<<<CC / 8, 256>>>(lw2, lb2);         // 64 CTAs
    k3c<<<BB, 512>>>();
    k4<<<BB * CC * 4, 256>>>(x, out);
}

// round 3
// speedup vs baseline: 1.0098x; 1.0098x over previous
#include <cuda_runtime.h>

#define BB 2
#define CC 512
#define HH 256
#define WW 256
#define EPSV 1e-5f

// ---------------- scratch (device globals; no allocations allowed) ----------
__device__ float g_y1[BB * CC * WW];     // [b][c][w]
__device__ float g_y2[BB * CC * HH];     // [b][c][h]
__device__ float g_dot[CC * BB];         // flat [c][b]; reinterpreted as num[b][k]
__device__ float g_h[BB * 2 * CC];       // [b][1024]
__device__ float g_logits[BB * CC];      // [b][c]
__device__ float g_scale[BB * CC];       // [b][c]

__device__ __forceinline__ float4 ldcs4(const float4* p) {
#if __CUDA_ARCH__ >= 320
    return __ldcs(p);
#else
    return *p;
#endif
}

// ============================================================================
// k1: per-(b,c) plane, compute y1[w] = sum_h x[h][w]*w1[h]  (column matvec)
//                         and y2[h] = sum_w x[h][w]*w2[w]  (row matvec)
// Single pass over x (268 MB). grid = B*C = 1024, block = 256.
// ============================================================================
__global__ __launch_bounds__(256) void k1(const float* __restrict__ x,
                                          const float* __restrict__ w1,
                                          const float* __restrict__ w2) {
    int bc = blockIdx.x;                 // b*CC + c
    int c  = bc & (CC - 1);
    const float4* plane = reinterpret_cast<const float4*>(x) + (size_t)bc * (HH * WW / 4);

    __shared__ float  w1s[HH];
    __shared__ float  w2s[WW];
    __shared__ float  y2part[HH][2];     // per-row partials from the two warp-halves
    __shared__ float4 acc1s[256];        // y1 partials, [r][q]

    int t = threadIdx.x;
    w1s[t] = w1[c * HH + t];             // w1: (C,1,H,1) -> c*H + h
    w2s[t] = w2[c * WW + t];             // w2: (C,1,1,W) -> c*W + w
    __syncthreads();

    int r    = t >> 6;
    int q    = t & 63;
    int lane = t & 31;
    int par  = (t >> 5) & 1;             // which half of the row this warp covers

    float4 w2q  = reinterpret_cast<const float4*>(w2s)[q];
    float4 acc1 = make_float4(0.f, 0.f, 0.f, 0.f);
    float  y2acc[2];

    #pragma unroll
    for (int half = 0; half < 2; ++half) {
        float acc = 0.f;
        #pragma unroll 8
        for (int ii = 0; ii < 32; ++ii) {
            int i   = half * 32 + ii;
            int row = 4 * i + r;
            float4 v   = ldcs4(&plane[row * (WW / 4) + q]);
            float  w1v = w1s[row];
            acc1.x = fmaf(v.x, w1v, acc1.x);
            acc1.y = fmaf(v.y, w1v, acc1.y);
            acc1.z = fmaf(v.z, w1v, acc1.z);
            acc1.w = fmaf(v.w, w1v, acc1.w);
            float p = v.x * w2q.x + v.y * w2q.y + v.z * w2q.z + v.w * w2q.w;
            #pragma unroll
            for (int off = 16; off; off >>= 1)
                p += __shfl_xor_sync(0xffffffffu, p, off);
            if (lane == ii) acc += p;    // all lanes hold the warp sum; lane ii banks it
        }
        y2acc[half] = acc;
    }

    // scatter y2 partials: lane l holds rows 4*l + r and 4*(32+l) + r
    y2part[4 * lane        + r][par] = y2acc[0];
    y2part[4 * (32 + lane) + r][par] = y2acc[1];
    acc1s[t] = acc1;                     // t == r*64 + q
    __syncthreads();

    g_y2[bc * HH + t] = y2part[t][0] + y2part[t][1];

    if (t < 64) {
        float4 a0 = acc1s[t], a1 = acc1s[64 + t], a2 = acc1s[128 + t], a3 = acc1s[192 + t];
        float4 o;
        o.x = (a0.x + a1.x) + (a2.x + a3.x);
        o.y = (a0.y + a1.y) + (a2.y + a3.y);
        o.z = (a0.z + a1.z) + (a2.z + a3.z);
        o.w = (a0.w + a1.w) + (a2.w + a3.w);
        reinterpret_cast<float4*>(g_y1 + (size_t)bc * WW)[t] = o;
    }
}

// ============================================================================
// block-wide sum over 256 threads (8 warps)
// ============================================================================
__device__ __forceinline__ float blockSum256(float v, float* sh) {
    #pragma unroll
    for (int off = 16; off; off >>= 1) v += __shfl_xor_sync(0xffffffffu, v, off);
    int lane = threadIdx.x & 31, w = threadIdx.x >> 5;
    if (lane == 0) sh[w] = v;
    __syncthreads();
    if (threadIdx.x == 0) {
        float s = sh[0];
        #pragma unroll
        for (int i = 1; i < 8; ++i) s += sh[i];
        sh[0] = s;
    }
    __syncthreads();
    float res = sh[0];
    __syncthreads();
    return res;
}

// ============================================================================
// k2: per-channel BN stats (biased, over B*256 = 512 values), ReLU, dot.
// grid = C = 512, block = 256. dot stored flat [c][b].
// ============================================================================
__global__ __launch_bounds__(256) void k2(const float* __restrict__ g1, const float* __restrict__ b1,
                                          const float* __restrict__ g2, const float* __restrict__ b2) {
    __shared__ float sh[8];
    int c = blockIdx.x, t = threadIdx.x;

    float a10 = g_y1[c * WW + t];
    float a11 = g_y1[CC * WW + c * WW + t];
    float a20 = g_y2[c * HH + t];
    float a21 = g_y2[CC * HH + c * HH + t];

    float S1 = blockSum256(a10 + a11, sh);
    float Q1 = blockSum256(a10 * a10 + a11 * a11, sh);
    float S2 = blockSum256(a20 + a21, sh);
    float Q2 = blockSum256(a20 * a20 + a21 * a21, sh);

    const float invn = 1.f / (float)(BB * WW);  // 1/512
    float m1 = S1 * invn, v1 = Q1 * invn - m1 * m1;
    float m2 = S2 * invn, v2 = Q2 * invn - m2 * m2;

    float r1 = rsqrtf(v1 + EPSV) * g1[c];
    float c1 = b1[c] - m1 * r1;
    float r2 = rsqrtf(v2 + EPSV) * g2[c];
    float c2 = b2[c] - m2 * r2;

    float x10 = fmaxf(0.f, fmaf(a10, r1, c1));
    float x11 = fmaxf(0.f, fmaf(a11, r1, c1));
    float x20 = fmaxf(0.f, fmaf(a20, r2, c2));
    float x21 = fmaxf(0.f, fmaf(a21, r2, c2));

    float d0 = blockSum256(x10 * x20, sh);
    float d1 = blockSum256(x11 * x21, sh);

    if (t == 0) {
        g_dot[c * BB + 0] = d0;
        g_dot[c * BB + 1] = d1;
    }
}

// ============================================================================
// k3a: out j of layer1. One block per output row, 128 threads, K=512.
// Each thread owns exactly one float4 of the weight row -> one coalesced burst.
// ============================================================================
__global__ __launch_bounds__(128) void k3a(const float* __restrict__ lw1, const float* __restrict__ lb1) {
    __shared__ float sh[4][2];
    int j = blockIdx.x, t = threadIdx.x;
    int lane = t & 31, w = t >> 5;

    float4 wq = __ldg(reinterpret_cast<const float4*>(lw1 + (size_t)j * CC) + t);
    float4 i0 = reinterpret_cast<const float4*>(g_dot)[t];           // batch 0 (flat k=4t)
    float4 i1 = reinterpret_cast<const float4*>(g_dot + CC)[t];      // batch 1

    float a0 = wq.x * i0.x + wq.y * i0.y + wq.z * i0.z + wq.w * i0.w;
    float a1 = wq.x * i1.x + wq.y * i1.y + wq.z * i1.z + wq.w * i1.w;
    #pragma unroll
    for (int off = 16; off; off >>= 1) {
        a0 += __shfl_xor_sync(0xffffffffu, a0, off);
        a1 += __shfl_xor_sync(0xffffffffu, a1, off);
    }
    if (lane == 0) { sh[w][0] = a0; sh[w][1] = a1; }
    __syncthreads();
    if (t == 0) {
        float bj = lb1[j];
        float s0 = sh[0][0] + sh[1][0] + sh[2][0] + sh[3][0];
        float s1 = sh[0][1] + sh[1][1] + sh[2][1] + sh[3][1];
        g_h[j]          = s0 + bj;
        g_h[2 * CC + j] = s1 + bj;
    }
}

// ============================================================================
// k3b: out j of layer2. One block per output row, 256 threads, K=1024.
// ============================================================================
__global__ __launch_bounds__(256) void k3b(const float* __restrict__ lw2, const float* __restrict__ lb2) {
    __shared__ float sh[8][2];
    int j = blockIdx.x, t = threadIdx.x;
    int lane = t & 31, w = t >> 5;

    float4 wq = __ldg(reinterpret_cast<const float4*>(lw2 + (size_t)j * 2 * CC) + t);
    float4 i0 = reinterpret_cast<const float4*>(g_h)[t];
    float4 i1 = reinterpret_cast<const float4*>(g_h + 2 * CC)[t];

    float a0 = wq.x * i0.x + wq.y * i0.y + wq.z * i0.z + wq.w * i0.w;
    float a1 = wq.x * i1.x + wq.y * i1.y + wq.z * i1.z + wq.w * i1.w;
    #pragma unroll
    for (int off = 16; off; off >>= 1) {
        a0 += __shfl_xor_sync(0xffffffffu, a0, off);
        a1 += __shfl_xor_sync(0xffffffffu, a1, off);
    }
    if (lane == 0) { sh[w][0] = a0; sh[w][1] = a1; }
    __syncthreads();
    if (t == 0) {
        float bj = lb2[j];
        float s0 = 0.f, s1 = 0.f;
        #pragma unroll
        for (int i = 0; i < 8; ++i) { s0 += sh[i][0]; s1 += sh[i][1]; }
        g_logits[j]      = s0 + bj;
        g_logits[CC + j] = s1 + bj;
    }
}

// ============================================================================
// k3c: stable softmax over axis 1. grid = B, block = 512.
// ============================================================================
__global__ __launch_bounds__(512) void k3c() {
    __shared__ float sh[16];
    int b = blockIdx.x, t = threadIdx.x;
    int lane = t & 31, w = t >> 5;

    float v = g_logits[b * CC + t];

    float m = v;
    #pragma unroll
    for (int off = 16; off; off >>= 1) m = fmaxf(m, __shfl_xor_sync(0xffffffffu, m, off));
    if (lane == 0) sh[w] = m;
    __syncthreads();
    if (t == 0) {
        float mm = sh[0];
        #pragma unroll
        for (int i = 1; i < 16; ++i) mm = fmaxf(mm, sh[i]);
        sh[0] = mm;
    }
    __syncthreads();
    m = sh[0];
    __syncthreads();

    float e = expf(v - m);
    float s = e;
    #pragma unroll
    for (int off = 16; off; off >>= 1) s += __shfl_xor_sync(0xffffffffu, s, off);
    if (lane == 0) sh[w] = s;
    __syncthreads();
    if (t == 0) {
        float ss = sh[0];
        #pragma unroll
        for (int i = 1; i < 16; ++i) ss += sh[i];
        sh[0] = ss;
    }
    __syncthreads();
    s = sh[0];

    g_scale[b * CC + t] = e / s;
}

// ============================================================================
// k4: out = x * scale[b,c]. grid = 8192 (8 CTAs per plane), block = 256,
// fully unrolled 8 x float4 per thread, streaming loads/stores.
// ============================================================================
__global__ __launch_bounds__(256) void k4(const float* __restrict__ x, float* __restrict__ out) {
    int blk  = blockIdx.x;
    int bc   = blk >> 3;                 // plane index == b*CC + c == scale index
    int part = blk & 7;
    float s = g_scale[bc];

    const float4* xp = reinterpret_cast<const float4*>(x)   + (size_t)bc * (HH * WW / 4) + part * 2048;
    float4*       op = reinterpret_cast<float4*>(out)       + (size_t)bc * (HH * WW / 4) + part * 2048;

    int t = threadIdx.x;
    #pragma unroll
    for (int i = 0; i < 8; ++i) {
        float4 v = ldcs4(&xp[i * 256 + t]);
        v.x *= s; v.y *= s; v.z *= s; v.w *= s;
        __stcs(&op[i * 256 + t], v);
    }
}

// ============================================================================
extern "C" void kernel_launch(void* const* d_in, const int* in_sizes, int n_in,
                              void* d_out, int out_size) {
    const float* x   = (const float*)d_in[0];
    const float* w1  = (const float*)d_in[1];
    const float* w2  = (const float*)d_in[2];
    const float* g1  = (const float*)d_in[3];
    const float* b1  = (const float*)d_in[4];
    const float* g2  = (const float*)d_in[5];
    const float* b2  = (const float*)d_in[6];
    const float* lw1 = (const float*)d_in[7];
    const float* lb1 = (const float*)d_in[8];
    const float* lw2 = (const float*)d_in[9];
    const float* lb2 = (const float*)d_in[10];
    float* out = (float*)d_out;

    k1<<<BB * CC, 256>>>(x, w1, w2);
    k2<<<CC, 256>>>(g1, b1, g2, b2);
    k3a<<<2 * CC, 128>>>(lw1, lb1);     // one block per output row
    k3b<<<CC, 256>>>(lw2, lb2);         // one block per output row
    k3c<<<BB, 512>>>();
    k4<<<BB * CC * 8, 256>>>(x, out);
}

// round 4
// speedup vs baseline: 1.0576x; 1.0474x over previous
#include <cuda_runtime.h>

#define BB 2
#define CC 512
#define HH 256
#define WW 256
#define EPSV 1e-5f
#define NCTA 148            // persistent-kernel grid: <= SM count on B300/GB300

// ---------------- scratch (device globals; no allocations allowed) ----------
__device__ float g_y1[BB * CC * WW];     // [b][c][w]
__device__ float g_y2[BB * CC * HH];     // [b][c][h]
__device__ float g_dot[CC * BB];         // flat [c][b]; linear view == num[b][k]
__device__ float g_h[BB * 2 * CC];       // [b][1024]
__device__ float g_logits[BB * CC];      // [b][c]
__device__ float g_scale[BB * CC];       // [b][c]

__device__ unsigned g_cnt[3];            // grid-barrier arrival counters
__device__ unsigned g_gen[3];            // grid-barrier generations (monotone)

__device__ __forceinline__ float4 ldcg4(const float4* p) {
    return __ldcg(p);
}
__device__ __forceinline__ void prefetchL2(const void* p) {
    asm volatile("prefetch.global.L2 [%0];" :: "l"(p));
}

// ============================================================================
// k1: per-(b,c) plane: y1[w] = sum_h x[h][w]*w1[h], y2[h] = sum_w x[h][w]*w2[w]
// Single pass over x (268 MB). grid = B*C = 1024, block = 256.
// Plain (caching) loads: the tail of this stream stays in L2 for k4 (which
// walks planes in REVERSE order to exploit it).
// ============================================================================
__global__ __launch_bounds__(256) void k1(const float* __restrict__ x,
                                          const float* __restrict__ w1,
                                          const float* __restrict__ w2) {
    int bc = blockIdx.x;                 // b*CC + c
    int c  = bc & (CC - 1);
    const float4* plane = reinterpret_cast<const float4*>(x) + (size_t)bc * (HH * WW / 4);

    __shared__ float  w1s[HH];
    __shared__ float  w2s[WW];
    __shared__ float  y2part[HH][2];
    __shared__ float4 acc1s[256];

    int t = threadIdx.x;
    w1s[t] = w1[c * HH + t];
    w2s[t] = w2[c * WW + t];
    __syncthreads();

    int r    = t >> 6;
    int q    = t & 63;
    int lane = t & 31;
    int par  = (t >> 5) & 1;

    float4 w2q  = reinterpret_cast<const float4*>(w2s)[q];
    float4 acc1 = make_float4(0.f, 0.f, 0.f, 0.f);
    float  y2acc[2];

    #pragma unroll
    for (int half = 0; half < 2; ++half) {
        float acc = 0.f;
        #pragma unroll 8
        for (int ii = 0; ii < 32; ++ii) {
            int i   = half * 32 + ii;
            int row = 4 * i + r;
            float4 v   = plane[row * (WW / 4) + q];
            float  w1v = w1s[row];
            acc1.x = fmaf(v.x, w1v, acc1.x);
            acc1.y = fmaf(v.y, w1v, acc1.y);
            acc1.z = fmaf(v.z, w1v, acc1.z);
            acc1.w = fmaf(v.w, w1v, acc1.w);
            float p = v.x * w2q.x + v.y * w2q.y + v.z * w2q.z + v.w * w2q.w;
            #pragma unroll
            for (int off = 16; off; off >>= 1)
                p += __shfl_xor_sync(0xffffffffu, p, off);
            if (lane == ii) acc += p;
        }
        y2acc[half] = acc;
    }

    y2part[4 * lane        + r][par] = y2acc[0];
    y2part[4 * (32 + lane) + r][par] = y2acc[1];
    acc1s[t] = acc1;
    __syncthreads();

    g_y2[bc * HH + t] = y2part[t][0] + y2part[t][1];

    if (t < 64) {
        float4 a0 = acc1s[t], a1 = acc1s[64 + t], a2 = acc1s[128 + t], a3 = acc1s[192 + t];
        float4 o;
        o.x = (a0.x + a1.x) + (a2.x + a3.x);
        o.y = (a0.y + a1.y) + (a2.y + a3.y);
        o.z = (a0.z + a1.z) + (a2.z + a3.z);
        o.w = (a0.w + a1.w) + (a2.w + a3.w);
        reinterpret_cast<float4*>(g_y1 + (size_t)bc * WW)[t] = o;
    }
}

// ============================================================================
// software grid barrier: all NCTA CTAs co-resident (grid == NCTA <= #SMs).
// One atomic arrival per CTA; release broadcast via plain volatile L2 reads.
// ============================================================================
__device__ __forceinline__ void gridbar(int i) {
    __syncthreads();
    if (threadIdx.x == 0) {
        __threadfence();                               // publish my writes
        volatile unsigned* genp = (volatile unsigned*)&g_gen[i];
        unsigned gen = *genp;                          // read BEFORE arriving
        unsigned arrived = atomicAdd(&g_cnt[i], 1u);
        if (arrived == NCTA - 1) {
            atomicExch(&g_cnt[i], 0u);                 // reset for next replay
            __threadfence();
            atomicAdd(&g_gen[i], 1u);                  // release
        } else {
            while (*genp == gen) { __nanosleep(32); }
        }
        __threadfence();                               // acquire others' writes
    }
    __syncthreads();
}

__device__ __forceinline__ float4 relu4(float4 a, float r, float c) {
    float4 o;
    o.x = fmaxf(0.f, fmaf(a.x, r, c));
    o.y = fmaxf(0.f, fmaf(a.y, r, c));
    o.z = fmaxf(0.f, fmaf(a.z, r, c));
    o.w = fmaxf(0.f, fmaf(a.w, r, c));
    return o;
}
__device__ __forceinline__ float hsum4(float4 a) { return (a.x + a.y) + (a.z + a.w); }
__device__ __forceinline__ float dotp4(float4 a, float4 b) {
    return a.x * b.x + a.y * b.y + a.z * b.z + a.w * b.w;
}

// ============================================================================
// kmid: fused BN+ReLU+dot -> linear1 -> linear2 -> softmax.
// Persistent, grid = NCTA, block = 256 (8 warps). 4 phases, 3 grid barriers.
// MLP weights (4 MB) are prefetched into L2 up front, overlapping phase A.
// ============================================================================
__global__ __launch_bounds__(256) void kmid(const float* __restrict__ g1, const float* __restrict__ b1,
                                            const float* __restrict__ g2, const float* __restrict__ b2,
                                            const float* __restrict__ lw1, const float* __restrict__ lb1,
                                            const float* __restrict__ lw2, const float* __restrict__ lb2) {
    int t    = threadIdx.x;
    int lane = t & 31;
    int wrp  = t >> 5;
    int gw   = blockIdx.x * 8 + wrp;                   // global warp id, 0..NCTA*8-1

    // ---- prefetch MLP weights into L2 (1 line per thread) ----
    {
        int gt = blockIdx.x * 256 + t;                 // 0..37887
        const char* p1 = (const char*)lw1;             // 2 MB = 16384 lines
        const char* p2 = (const char*)lw2;             // 2 MB = 16384 lines
        if (gt < 16384)               prefetchL2(p1 + (size_t)gt * 128);
        else if (gt < 32768)          prefetchL2(p2 + (size_t)(gt - 16384) * 128);
    }

    // ---- phase A: per-channel BN stats + ReLU + dot (one warp per channel) --
    if (gw < CC) {
        int c = gw;
        const float4* p10 = reinterpret_cast<const float4*>(g_y1 + c * WW);
        const float4* p11 = reinterpret_cast<const float4*>(g_y1 + CC * WW + c * WW);
        const float4* p20 = reinterpret_cast<const float4*>(g_y2 + c * HH);
        const float4* p21 = reinterpret_cast<const float4*>(g_y2 + CC * HH + c * HH);

        float4 a10a = ldcg4(p10 + lane), a10b = ldcg4(p10 + lane + 32);
        float4 a11a = ldcg4(p11 + lane), a11b = ldcg4(p11 + lane + 32);
        float4 a20a = ldcg4(p20 + lane), a20b = ldcg4(p20 + lane + 32);
        float4 a21a = ldcg4(p21 + lane), a21b = ldcg4(p21 + lane + 32);

        float s1 = hsum4(a10a) + hsum4(a10b) + hsum4(a11a) + hsum4(a11b);
        float q1 = dotp4(a10a, a10a) + dotp4(a10b, a10b) + dotp4(a11a, a11a) + dotp4(a11b, a11b);
        float s2 = hsum4(a20a) + hsum4(a20b) + hsum4(a21a) + hsum4(a21b);
        float q2 = dotp4(a20a, a20a) + dotp4(a20b, a20b) + dotp4(a21a, a21a) + dotp4(a21b, a21b);

        #pragma unroll
        for (int off = 16; off; off >>= 1) {
            s1 += __shfl_xor_sync(0xffffffffu, s1, off);
            q1 += __shfl_xor_sync(0xffffffffu, q1, off);
            s2 += __shfl_xor_sync(0xffffffffu, s2, off);
            q2 += __shfl_xor_sync(0xffffffffu, q2, off);
        }

        const float invn = 1.f / (float)(BB * WW);
        float m1 = s1 * invn, v1 = q1 * invn - m1 * m1;
        float m2 = s2 * invn, v2 = q2 * invn - m2 * m2;
        float r1 = rsqrtf(v1 + EPSV) * g1[c];
        float c1 = b1[c] - m1 * r1;
        float r2 = rsqrtf(v2 + EPSV) * g2[c];
        float c2 = b2[c] - m2 * r2;

        float d0 = dotp4(relu4(a10a, r1, c1), relu4(a20a, r2, c2))
                 + dotp4(relu4(a10b, r1, c1), relu4(a20b, r2, c2));
        float d1 = dotp4(relu4(a11a, r1, c1), relu4(a21a, r2, c2))
                 + dotp4(relu4(a11b, r1, c1), relu4(a21b, r2, c2));
        #pragma unroll
        for (int off = 16; off; off >>= 1) {
            d0 += __shfl_xor_sync(0xffffffffu, d0, off);
            d1 += __shfl_xor_sync(0xffffffffu, d1, off);
        }
        if (lane == 0) {
            g_dot[c * BB + 0] = d0;
            g_dot[c * BB + 1] = d1;
        }
    }

    gridbar(0);

    // ---- phase B: layer1, one warp per output row j (K=512) ----
    if (gw < 2 * CC) {
        int j = gw;
        const float4* wr = reinterpret_cast<const float4*>(lw1 + (size_t)j * CC);
        const float4* i0 = reinterpret_cast<const float4*>(g_dot);        // num[0][:]
        const float4* i1 = reinterpret_cast<const float4*>(g_dot + CC);   // num[1][:]
        float a0 = 0.f, a1 = 0.f;
        #pragma unroll
        for (int i = 0; i < 4; ++i) {
            float4 wq = __ldg(wr + lane + 32 * i);
            float4 v0 = ldcg4(i0 + lane + 32 * i);
            float4 v1 = ldcg4(i1 + lane + 32 * i);
            a0 += dotp4(wq, v0);
            a1 += dotp4(wq, v1);
        }
        #pragma unroll
        for (int off = 16; off; off >>= 1) {
            a0 += __shfl_xor_sync(0xffffffffu, a0, off);
            a1 += __shfl_xor_sync(0xffffffffu, a1, off);
        }
        if (lane == 0) {
            float bj = lb1[j];
            g_h[j]          = a0 + bj;
            g_h[2 * CC + j] = a1 + bj;
        }
    }

    gridbar(1);

    // ---- phase C: layer2, one warp per output row j (K=1024) ----
    if (gw < CC) {
        int j = gw;
        const float4* wr = reinterpret_cast<const float4*>(lw2 + (size_t)j * 2 * CC);
        const float4* i0 = reinterpret_cast<const float4*>(g_h);
        const float4* i1 = reinterpret_cast<const float4*>(g_h + 2 * CC);
        float a0 = 0.f, a1 = 0.f;
        #pragma unroll
        for (int i = 0; i < 8; ++i) {
            float4 wq = __ldg(wr + lane + 32 * i);
            float4 v0 = ldcg4(i0 + lane + 32 * i);
            float4 v1 = ldcg4(i1 + lane + 32 * i);
            a0 += dotp4(wq, v0);
            a1 += dotp4(wq, v1);
        }
        #pragma unroll
        for (int off = 16; off; off >>= 1) {
            a0 += __shfl_xor_sync(0xffffffffu, a0, off);
            a1 += __shfl_xor_sync(0xffffffffu, a1, off);
        }
        if (lane == 0) {
            float bj = lb2[j];
            g_logits[j]      = a0 + bj;
            g_logits[CC + j] = a1 + bj;
        }
    }

    gridbar(2);

    // ---- phase D: softmax over c per batch; CTA 0 only ----
    if (blockIdx.x == 0) {
        __shared__ float sh[8];
        #pragma unroll
        for (int b = 0; b < BB; ++b) {
            float v0 = __ldcg(&g_logits[b * CC + t]);
            float v1 = __ldcg(&g_logits[b * CC + 256 + t]);

            float m = fmaxf(v0, v1);
            #pragma unroll
            for (int off = 16; off; off >>= 1) m = fmaxf(m, __shfl_xor_sync(0xffffffffu, m, off));
            if (lane == 0) sh[wrp] = m;
            __syncthreads();
            if (t == 0) {
                float mm = sh[0];
                #pragma unroll
                for (int i = 1; i < 8; ++i) mm = fmaxf(mm, sh[i]);
                sh[0] = mm;
            }
            __syncthreads();
            m = sh[0];
            __syncthreads();

            float e0 = expf(v0 - m), e1 = expf(v1 - m);
            float s = e0 + e1;
            #pragma unroll
            for (int off = 16; off; off >>= 1) s += __shfl_xor_sync(0xffffffffu, s, off);
            if (lane == 0) sh[wrp] = s;
            __syncthreads();
            if (t == 0) {
                float ss = sh[0];
                #pragma unroll
                for (int i = 1; i < 8; ++i) ss += sh[i];
                sh[0] = ss;
            }
            __syncthreads();
            s = sh[0];
            __syncthreads();

            float inv = 1.f / s;
            g_scale[b * CC + t]       = e0 * inv;
            g_scale[b * CC + 256 + t] = e1 * inv;
        }
    }
}

// ============================================================================
// k4: out = x * scale[b,c]. Planes walked in REVERSE so that the tail of k1's
// read stream (still L2-resident) is hit first. Streaming stores keep the
// output from evicting x.
// ============================================================================
__global__ __launch_bounds__(256) void k4(const float* __restrict__ x, float* __restrict__ out) {
    int idx  = (BB * CC * 8 - 1) - blockIdx.x;   // reversed schedule
    int bc   = idx >> 3;
    int part = idx & 7;
    float s = __ldcg(&g_scale[bc]);

    const float4* xp = reinterpret_cast<const float4*>(x)   + (size_t)bc * (HH * WW / 4) + part * 2048;
    float4*       op = reinterpret_cast<float4*>(out)       + (size_t)bc * (HH * WW / 4) + part * 2048;

    int t = threadIdx.x;
    #pragma unroll
    for (int i = 0; i < 8; ++i) {
        float4 v = xp[i * 256 + t];
        v.x *= s; v.y *= s; v.z *= s; v.w *= s;
        __stcs(&op[i * 256 + t], v);
    }
}

// ============================================================================
extern "C" void kernel_launch(void* const* d_in, const int* in_sizes, int n_in,
                              void* d_out, int out_size) {
    const float* x   = (const float*)d_in[0];
    const float* w1  = (const float*)d_in[1];
    const float* w2  = (const float*)d_in[2];
    const float* g1  = (const float*)d_in[3];
    const float* b1  = (const float*)d_in[4];
    const float* g2  = (const float*)d_in[5];
    const float* b2  = (const float*)d_in[6];
    const float* lw1 = (const float*)d_in[7];
    const float* lb1 = (const float*)d_in[8];
    const float* lw2 = (const float*)d_in[9];
    const float* lb2 = (const float*)d_in[10];
    float* out = (float*)d_out;

    k1<<<BB * CC, 256>>>(x, w1, w2);
    kmid<<<NCTA, 256>>>(g1, b1, g2, b2, lw1, lb1, lw2, lb2);
    k4<<<BB * CC * 8, 256>>>(x, out);
}